// round 10
// baseline (speedup 1.0000x reference)
#include <cuda_runtime.h>
#include <cuda_fp16.h>
#include <cstdint>
#include <math.h>

// DataTransformer via mma.sync fp16 (fp32 accum), gate folded into MMA by
// pre-scaling A fragments with sim (fp16):
//   out[r,e] = sum_t sim_rt * (x_r . W_t[e,:]) + sum_t sim_rt*b_t[e] + x[r,e]
// CTA tile 128x128, 256 thr, warp grid 4(M)x2(N), warp tile 32x64. 2 CTAs/SM.

#define D_DIM   128
#define T_DIM   8
#define MTILE   128
#define NTILE   128
#define THREADS 256
#define NROWS   65536

// fp16 scratch (static __device__ arrays: allowed scratch form)
__device__ __half g_xhi[NROWS * D_DIM];
__device__ __half g_whi[T_DIM * D_DIM * D_DIM];

// ---- smem layout (bytes). Tiles: 256 B rows + XOR-of-16B-chunk swizzle ----
#define OFF_X    0u         // 128x128 fp16 = 32768
#define OFF_W    32768u     // 2 buffers x (128x128 fp16 = 32768) = 65536
#define OFF_P    98304u     // 8*128 f32 = 4096
#define OFF_SIM  102400u    // 128*9*4 = 4608 (fp32, stride 9)
#define OFF_SIMH 107008u    // 128*8*4 = 4096 (half2 duplicated)
#define OFF_BH   111104u    // 8*64*4 = 2048 (half2 col-pairs)
#define OFF_PN2  113152u    // 8 f32
#define SMEM_TOTAL 113184

__device__ __forceinline__ uint32_t smem_u32(const void* p) {
    uint32_t a;
    asm("{ .reg .u64 t; cvta.to.shared.u64 t, %1; cvt.u32.u64 %0, t; }" : "=r"(a) : "l"(p));
    return a;
}

#define CP_ASYNC16(dst, src) \
    asm volatile("cp.async.cg.shared.global [%0], [%1], 16;" :: "r"(dst), "l"(src) : "memory")
#define CP_COMMIT() asm volatile("cp.async.commit_group;" ::: "memory")
#define CP_WAIT1()  asm volatile("cp.async.wait_group 1;" ::: "memory")
#define CP_WAIT0()  asm volatile("cp.async.wait_group 0;" ::: "memory")

#define LDM4(r0, r1, r2, r3, addr) \
    asm volatile("ldmatrix.sync.aligned.m8n8.x4.shared.b16 {%0,%1,%2,%3}, [%4];" \
        : "=r"(r0), "=r"(r1), "=r"(r2), "=r"(r3) : "r"(addr))

#define MMA16816(d, a0, a1, a2, a3, b0, b1) \
    asm volatile("mma.sync.aligned.m16n8k16.row.col.f32.f16.f16.f32 " \
        "{%0,%1,%2,%3}, {%4,%5,%6,%7}, {%8,%9}, {%0,%1,%2,%3};" \
        : "+f"((d)[0]), "+f"((d)[1]), "+f"((d)[2]), "+f"((d)[3]) \
        : "r"(a0), "r"(a1), "r"(a2), "r"(a3), "r"(b0), "r"(b1))

#define HMUL2(d, a, s) \
    asm("mul.rn.f16x2 %0, %1, %2;" : "=r"(d) : "r"(a), "r"(s))

// swizzled byte offset of 16B chunk (r, c), c in [0,16), 256 B rows
__device__ __forceinline__ uint32_t swz(int r, int c) {
    return (uint32_t)(r * 256 + ((c ^ (r & 7)) << 4));
}

// ===================== Kernel 1: fp32 -> fp16 preconvert =====================
__global__ void conv_kernel(const float* __restrict__ x, const float* __restrict__ W)
{
    const int W4 = T_DIM * D_DIM * D_DIM / 4;   // 32768 float4
    const int X4 = NROWS * D_DIM / 4;           // 2097152 float4
    for (int i = blockIdx.x * blockDim.x + threadIdx.x; i < W4 + X4;
         i += gridDim.x * blockDim.x) {
        bool isw = (i < W4);
        float4 v = isw ? reinterpret_cast<const float4*>(W)[i]
                       : reinterpret_cast<const float4*>(x)[i - W4];
        float vf[4] = {v.x, v.y, v.z, v.w};
        uint32_t hw[4];
#pragma unroll
        for (int e = 0; e < 4; e++)
            hw[e] = (uint32_t)__half_as_ushort(__float2half_rn(vf[e]));
        uint2 hv = make_uint2(hw[0] | (hw[1] << 16), hw[2] | (hw[3] << 16));
        if (isw) reinterpret_cast<uint2*>(g_whi)[i] = hv;
        else     reinterpret_cast<uint2*>(g_xhi)[i - W4] = hv;
    }
}

// ===================== Kernel 2: GEMM + gating + fold =====================
__device__ __forceinline__ void issue_w_tile(uint32_t sb, uint32_t wbuf, int t, int tid)
{
    const size_t wb = (size_t)t * (D_DIM * D_DIM);
#pragma unroll
    for (int k = 0; k < 8; k++) {
        int ci = tid + k * THREADS;          // 2048 chunks (128 rows x 16)
        int r = ci >> 4, c = ci & 15;
        CP_ASYNC16(sb + wbuf + swz(r, c), g_whi + wb + r * D_DIM + c * 8);
    }
}

__global__ void __launch_bounds__(THREADS, 2)
dt_mma_kernel(const float* __restrict__ x,
              const float* __restrict__ b,
              const float* __restrict__ p,
              float* __restrict__ out)
{
    extern __shared__ char smem[];
    const uint32_t sb = smem_u32(smem);
    const int tid  = threadIdx.x;
    const int wid  = tid >> 5;
    const int lane = tid & 31;
    const int row0 = blockIdx.x * MTILE;

    float*     s_p    = reinterpret_cast<float*>(smem + OFF_P);
    float*     s_sim  = reinterpret_cast<float*>(smem + OFF_SIM);
    uint32_t*  s_simh = reinterpret_cast<uint32_t*>(smem + OFF_SIMH);
    uint32_t*  s_bh   = reinterpret_cast<uint32_t*>(smem + OFF_BH);
    float*     s_pn2  = reinterpret_cast<float*>(smem + OFF_PN2);

    // p to smem; b packed as half2 col-pairs
#pragma unroll
    for (int i = tid; i < T_DIM * D_DIM; i += THREADS) s_p[i] = p[i];
#pragma unroll
    for (int i = tid; i < T_DIM * 64; i += THREADS) {
        int t = i >> 6, cp = i & 63;
        float b0 = b[t * D_DIM + 2 * cp], b1 = b[t * D_DIM + 2 * cp + 1];
        __half2 h = __floats2half2_rn(b0, b1);
        s_bh[i] = *reinterpret_cast<uint32_t*>(&h);
    }

    // Group 0: x tile + W(0); Group 1: W(1)
#pragma unroll
    for (int k = 0; k < 8; k++) {
        int ci = tid + k * THREADS;          // 2048 chunks (128 rows x 16)
        int r = ci >> 4, c = ci & 15;
        CP_ASYNC16(sb + OFF_X + swz(r, c), g_xhi + (size_t)(row0 + r) * D_DIM + c * 8);
    }
    issue_w_tile(sb, OFF_W, 0, tid);
    CP_COMMIT();
    issue_w_tile(sb, OFF_W + 32768u, 1, tid);
    CP_COMMIT();

    __syncthreads();   // s_p visible for gating

    // ---- Gating (exact fp32, overlapped with cp.async) ----
    if (tid < T_DIM) {
        float pn2 = 0.f;
#pragma unroll 16
        for (int d = 0; d < D_DIM; d++) {
            float pv = s_p[tid * D_DIM + d];
            pn2 = fmaf(pv, pv, pn2);
        }
        s_pn2[tid] = pn2;
    }
    float dots[T_DIM], xn2 = 0.f;
    if (tid < MTILE) {
#pragma unroll
        for (int t = 0; t < T_DIM; t++) dots[t] = 0.f;
        const float4* xr = reinterpret_cast<const float4*>(x + (size_t)(row0 + tid) * D_DIM);
#pragma unroll 4
        for (int i = 0; i < 32; i++) {
            float4 v = xr[i];
            float vf[4] = {v.x, v.y, v.z, v.w};
#pragma unroll
            for (int e = 0; e < 4; e++) {
                float xv = vf[e];
                xn2 = fmaf(xv, xv, xn2);
                int d = i * 4 + e;
#pragma unroll
                for (int t = 0; t < T_DIM; t++)
                    dots[t] = fmaf(xv, s_p[t * D_DIM + d], dots[t]);
            }
        }
    }
    __syncthreads();   // s_pn2 ready
    if (tid < MTILE) {
        float xn = sqrtf(xn2);
        float cosv[T_DIM], m = -1e30f;
#pragma unroll
        for (int t = 0; t < T_DIM; t++) {
            cosv[t] = dots[t] / (xn * sqrtf(s_pn2[t]));
            m = fmaxf(m, cosv[t]);
        }
        float ev[T_DIM], sum = 0.f;
#pragma unroll
        for (int t = 0; t < T_DIM; t++) { ev[t] = expf(cosv[t] - m); sum += ev[t]; }
        float inv = 1.f / sum;
#pragma unroll
        for (int t = 0; t < T_DIM; t++) {
            float sv = ev[t] * inv;
            s_sim[tid * 9 + t] = sv;
            __half2 h = __floats2half2_rn(sv, sv);
            s_simh[tid * 8 + t] = *reinterpret_cast<uint32_t*>(&h);
        }
    }

    CP_WAIT1();        // group 0 (x + W0) complete
    __syncthreads();   // tiles + sim/simh visible

    // ---- Warp tiling: 4(M) x 2(N), warp tile 32x64 ----
    const int wm = wid & 3, wn = wid >> 2;
    const int mbw = wm * 32, nbw = wn * 64;

    // ldmatrix per-lane address parts (swizzled)
    const uint32_t arowb = (uint32_t)((mbw + (lane & 15)) * 256);
    const int     achnk  = lane >> 4;            // 0/1
    const uint32_t browb = (uint32_t)((nbw + (lane & 7) + ((lane >> 4) << 3)) * 256);
    const int     bchnk  = (lane >> 3) & 1;
    const int     bank   = lane & 7;
    const int rql = lane >> 2;
    const int cpl = (lane & 3) * 2;

    float acc[2][8][4];
#pragma unroll
    for (int i = 0; i < 2; i++)
#pragma unroll
        for (int j = 0; j < 8; j++)
#pragma unroll
            for (int e = 0; e < 4; e++) acc[i][j][e] = 0.f;

    for (int t = 0; t < T_DIM; t++) {
        const uint32_t wb = OFF_W + (uint32_t)(t & 1) * 32768u;

        // per-t row scales (duplicated half2), rows mbw+rql, +8, +16, +24
        const uint32_t sA0 = s_simh[(mbw + rql) * 8 + t];
        const uint32_t sA1 = s_simh[(mbw + 8 + rql) * 8 + t];
        const uint32_t sA2 = s_simh[(mbw + 16 + rql) * 8 + t];
        const uint32_t sA3 = s_simh[(mbw + 24 + rql) * 8 + t];

#pragma unroll
        for (int k = 0; k < 8; k++) {
            const uint32_t aoff = arowb + (uint32_t)((((2 * k + achnk) ^ bank)) << 4);
            const uint32_t boff = browb + (uint32_t)((((2 * k + bchnk) ^ bank)) << 4);

            uint32_t a0, a1, a2, a3, a4, a5, a6, a7;
            LDM4(a0, a1, a2, a3, sb + OFF_X + aoff);
            LDM4(a4, a5, a6, a7, sb + OFF_X + aoff + 16u * 256u);
            // prescale by sim (row-uniform per fragment register)
            HMUL2(a0, a0, sA0); HMUL2(a2, a2, sA0);
            HMUL2(a1, a1, sA1); HMUL2(a3, a3, sA1);
            HMUL2(a4, a4, sA2); HMUL2(a6, a6, sA2);
            HMUL2(a5, a5, sA3); HMUL2(a7, a7, sA3);

            uint32_t b0, b1, b2, b3, b4, b5, b6, b7;
            LDM4(b0, b1, b2, b3, sb + wb + boff);
            LDM4(b4, b5, b6, b7, sb + wb + boff + 16u * 256u);
            uint32_t c0, c1, c2, c3, c4, c5, c6, c7;
            LDM4(c0, c1, c2, c3, sb + wb + boff + 32u * 256u);
            LDM4(c4, c5, c6, c7, sb + wb + boff + 48u * 256u);

            MMA16816(acc[0][0], a0, a1, a2, a3, b0, b1);
            MMA16816(acc[0][1], a0, a1, a2, a3, b2, b3);
            MMA16816(acc[0][2], a0, a1, a2, a3, b4, b5);
            MMA16816(acc[0][3], a0, a1, a2, a3, b6, b7);
            MMA16816(acc[0][4], a0, a1, a2, a3, c0, c1);
            MMA16816(acc[0][5], a0, a1, a2, a3, c2, c3);
            MMA16816(acc[0][6], a0, a1, a2, a3, c4, c5);
            MMA16816(acc[0][7], a0, a1, a2, a3, c6, c7);
            MMA16816(acc[1][0], a4, a5, a6, a7, b0, b1);
            MMA16816(acc[1][1], a4, a5, a6, a7, b2, b3);
            MMA16816(acc[1][2], a4, a5, a6, a7, b4, b5);
            MMA16816(acc[1][3], a4, a5, a6, a7, b6, b7);
            MMA16816(acc[1][4], a4, a5, a6, a7, c0, c1);
            MMA16816(acc[1][5], a4, a5, a6, a7, c2, c3);
            MMA16816(acc[1][6], a4, a5, a6, a7, c4, c5);
            MMA16816(acc[1][7], a4, a5, a6, a7, c6, c7);
        }

        // pipeline: refill the buffer we just finished with W(t+2)
        if (t < T_DIM - 2) {
            __syncthreads();
            issue_w_tile(sb, OFF_W + (uint32_t)(t & 1) * 32768u, t + 2, tid);
            CP_COMMIT();
        }
        if (t < T_DIM - 1) {
            if (t < T_DIM - 2) { CP_WAIT1(); } else { CP_WAIT0(); }
            __syncthreads();
        }
    }

    // ---- Epilogue: bias (sum_t sim_t*b_t, fp32) + residual + store ----
    float sm[4][T_DIM];
#pragma unroll
    for (int t = 0; t < T_DIM; t++) {
        sm[0][t] = s_sim[(mbw + rql) * 9 + t];
        sm[1][t] = s_sim[(mbw + 8 + rql) * 9 + t];
        sm[2][t] = s_sim[(mbw + 16 + rql) * 9 + t];
        sm[3][t] = s_sim[(mbw + 24 + rql) * 9 + t];
    }
#pragma unroll
    for (int nt = 0; nt < 8; nt++) {
        const int c = nbw + nt * 8 + cpl;            // global col (even)
        const int cpidx = c >> 1;
        float bs[4][2];
#pragma unroll
        for (int r = 0; r < 4; r++) { bs[r][0] = 0.f; bs[r][1] = 0.f; }
#pragma unroll
        for (int t = 0; t < T_DIM; t++) {
            uint32_t bh = s_bh[t * 64 + cpidx];
            __half2 h = *reinterpret_cast<__half2*>(&bh);
            float b0 = __low2float(h), b1 = __high2float(h);
#pragma unroll
            for (int r = 0; r < 4; r++) {
                bs[r][0] = fmaf(sm[r][t], b0, bs[r][0]);
                bs[r][1] = fmaf(sm[r][t], b1, bs[r][1]);
            }
        }
#pragma unroll
        for (int mt = 0; mt < 2; mt++) {
            const int rg0 = row0 + mbw + mt * 16 + rql;
            const int rg1 = rg0 + 8;
            float2 xv0 = *reinterpret_cast<const float2*>(x + (size_t)rg0 * D_DIM + c);
            float2 o0 = make_float2(acc[mt][nt][0] + bs[mt * 2][0] + xv0.x,
                                    acc[mt][nt][1] + bs[mt * 2][1] + xv0.y);
            *reinterpret_cast<float2*>(out + (size_t)rg0 * D_DIM + c) = o0;
            float2 xv1 = *reinterpret_cast<const float2*>(x + (size_t)rg1 * D_DIM + c);
            float2 o1 = make_float2(acc[mt][nt][2] + bs[mt * 2 + 1][0] + xv1.x,
                                    acc[mt][nt][3] + bs[mt * 2 + 1][1] + xv1.y);
            *reinterpret_cast<float2*>(out + (size_t)rg1 * D_DIM + c) = o1;
        }
    }
}

extern "C" void kernel_launch(void* const* d_in, const int* in_sizes, int n_in,
                              void* d_out, int out_size)
{
    (void)n_in; (void)out_size;
    const float* x = (const float*)d_in[0];   // [B,S,D]
    const float* W = (const float*)d_in[1];   // [T,D,D]
    const float* b = (const float*)d_in[2];   // [T,D]
    const float* p = (const float*)d_in[3];   // [T,1,D]
    float* out = (float*)d_out;

    const int nrows = in_sizes[0] / D_DIM;    // 65536
    const int grid  = nrows / MTILE;          // 512

    conv_kernel<<<2048, 256>>>(x, W);

    cudaFuncSetAttribute(dt_mma_kernel,
                         cudaFuncAttributeMaxDynamicSharedMemorySize, SMEM_TOTAL);
    dt_mma_kernel<<<grid, THREADS, SMEM_TOTAL>>>(x, b, p, out);
}

// round 11
// speedup vs baseline: 1.1684x; 1.1684x over previous
#include <cuda_runtime.h>
#include <cuda_fp16.h>
#include <cstdint>
#include <math.h>

// DataTransformer via mma.sync, pure fp16 single-pass GEMM (fp32 accumulate),
// with gating softmax computed by a separate warp-per-row kernel:
//   out[r,e] = sum_t sim_rt * (x_r . W_t[e,:] + b_t[e]) + x[r,e]
// CTA tile: 128 rows x 64 cols, 256 threads, warp grid 4x2 (tile 32x32). 2 CTAs/SM.

#define D_DIM   128
#define T_DIM   8
#define MTILE   128
#define NTILE   64
#define THREADS 256
#define NROWS   65536

// scratch (static __device__ arrays: allowed scratch form)
__device__ __half g_xhi[NROWS * D_DIM];
__device__ __half g_whi[T_DIM * D_DIM * D_DIM];
__device__ float  g_sim[NROWS * T_DIM];

// ---- smem layout (bytes). Tiles use 256 B rows + XOR-of-16B-chunk swizzle ----
#define OFF_X    0u         // 128x128 fp16 = 32768
#define OFF_W    32768u     // 2 buffers x (64x128 fp16 = 16384) = 32768
#define OFF_B    65536u     // 8*64 f32 = 2048
#define OFF_SIM  67584u     // 128*9*4 = 4608 (fp32, stride 9)
#define SMEM_TOTAL 72192

__device__ __forceinline__ uint32_t smem_u32(const void* p) {
    uint32_t a;
    asm("{ .reg .u64 t; cvta.to.shared.u64 t, %1; cvt.u32.u64 %0, t; }" : "=r"(a) : "l"(p));
    return a;
}

#define CP_ASYNC16(dst, src) \
    asm volatile("cp.async.cg.shared.global [%0], [%1], 16;" :: "r"(dst), "l"(src) : "memory")
#define CP_COMMIT() asm volatile("cp.async.commit_group;" ::: "memory")
#define CP_WAIT1()  asm volatile("cp.async.wait_group 1;" ::: "memory")
#define CP_WAIT0()  asm volatile("cp.async.wait_group 0;" ::: "memory")

#define LDM4(r0, r1, r2, r3, addr) \
    asm volatile("ldmatrix.sync.aligned.m8n8.x4.shared.b16 {%0,%1,%2,%3}, [%4];" \
        : "=r"(r0), "=r"(r1), "=r"(r2), "=r"(r3) : "r"(addr))

#define MMA16816(d, a0, a1, a2, a3, b0, b1) \
    asm volatile("mma.sync.aligned.m16n8k16.row.col.f32.f16.f16.f32 " \
        "{%0,%1,%2,%3}, {%4,%5,%6,%7}, {%8,%9}, {%0,%1,%2,%3};" \
        : "+f"((d)[0]), "+f"((d)[1]), "+f"((d)[2]), "+f"((d)[3]) \
        : "r"(a0), "r"(a1), "r"(a2), "r"(a3), "r"(b0), "r"(b1))

// swizzled byte offset of 16B chunk (r, c), c in [0,16), 256 B rows
__device__ __forceinline__ uint32_t swz(int r, int c) {
    return (uint32_t)(r * 256 + ((c ^ (r & 7)) << 4));
}

// ===================== Kernel 1: fp32 -> fp16 preconvert =====================
__global__ void conv_kernel(const float* __restrict__ x, const float* __restrict__ W)
{
    const int W4 = T_DIM * D_DIM * D_DIM / 4;   // 32768 float4
    const int X4 = NROWS * D_DIM / 4;           // 2097152 float4
    for (int i = blockIdx.x * blockDim.x + threadIdx.x; i < W4 + X4;
         i += gridDim.x * blockDim.x) {
        bool isw = (i < W4);
        float4 v = isw ? reinterpret_cast<const float4*>(W)[i]
                       : reinterpret_cast<const float4*>(x)[i - W4];
        float vf[4] = {v.x, v.y, v.z, v.w};
        uint32_t hw[4];
#pragma unroll
        for (int e = 0; e < 4; e++)
            hw[e] = (uint32_t)__half_as_ushort(__float2half_rn(vf[e]));
        uint2 hv = make_uint2(hw[0] | (hw[1] << 16), hw[2] | (hw[3] << 16));
        if (isw) reinterpret_cast<uint2*>(g_whi)[i] = hv;
        else     reinterpret_cast<uint2*>(g_xhi)[i - W4] = hv;
    }
}

// ===================== Kernel 2: gating softmax, one warp per row =====================
__global__ void gate_kernel(const float* __restrict__ x, const float* __restrict__ p)
{
    const int wid  = threadIdx.x >> 5;
    const int lane = threadIdx.x & 31;
    const int row  = blockIdx.x * 8 + wid;

    const float4 xv = reinterpret_cast<const float4*>(x + (size_t)row * D_DIM)[lane];
    float xn2 = xv.x * xv.x + xv.y * xv.y + xv.z * xv.z + xv.w * xv.w;
    float dots[T_DIM], pn2[T_DIM];
#pragma unroll
    for (int t = 0; t < T_DIM; t++) {
        const float4 pv = reinterpret_cast<const float4*>(p + t * D_DIM)[lane];
        dots[t] = xv.x * pv.x + xv.y * pv.y + xv.z * pv.z + xv.w * pv.w;
        pn2[t]  = pv.x * pv.x + pv.y * pv.y + pv.z * pv.z + pv.w * pv.w;
    }
#pragma unroll
    for (int o = 16; o > 0; o >>= 1) {
        xn2 += __shfl_xor_sync(0xffffffffu, xn2, o);
#pragma unroll
        for (int t = 0; t < T_DIM; t++) {
            dots[t] += __shfl_xor_sync(0xffffffffu, dots[t], o);
            pn2[t]  += __shfl_xor_sync(0xffffffffu, pn2[t], o);
        }
    }
    const float xn = sqrtf(xn2);
    float cosv[T_DIM], m = -1e30f;
#pragma unroll
    for (int t = 0; t < T_DIM; t++) {
        cosv[t] = dots[t] / (xn * sqrtf(pn2[t]));
        m = fmaxf(m, cosv[t]);
    }
    float ev[T_DIM], sum = 0.f;
#pragma unroll
    for (int t = 0; t < T_DIM; t++) { ev[t] = expf(cosv[t] - m); sum += ev[t]; }
    const float inv = 1.f / sum;
    if (lane == 0) {
        float4 s0 = make_float4(ev[0] * inv, ev[1] * inv, ev[2] * inv, ev[3] * inv);
        float4 s1 = make_float4(ev[4] * inv, ev[5] * inv, ev[6] * inv, ev[7] * inv);
        reinterpret_cast<float4*>(g_sim + (size_t)row * T_DIM)[0] = s0;
        reinterpret_cast<float4*>(g_sim + (size_t)row * T_DIM)[1] = s1;
    }
}

// ===================== Kernel 3: GEMM + fold =====================
__device__ __forceinline__ void issue_w_tile(uint32_t sb, uint32_t wbuf, int t, int nbase, int tid)
{
    const size_t wb = (size_t)t * (D_DIM * D_DIM) + (size_t)nbase * D_DIM;
#pragma unroll
    for (int k = 0; k < 4; k++) {
        int ci = tid + k * THREADS;          // 16B chunk index, 1024 per tile (64 rows x 16)
        int r = ci >> 4, c = ci & 15;
        CP_ASYNC16(sb + wbuf + swz(r, c), g_whi + wb + r * D_DIM + c * 8);
    }
}

__global__ void __launch_bounds__(THREADS, 2)
dt_mma_kernel(const float* __restrict__ x,
              const float* __restrict__ b,
              float* __restrict__ out)
{
    extern __shared__ char smem[];
    const uint32_t sb = smem_u32(smem);
    const int tid  = threadIdx.x;
    const int wid  = tid >> 5;
    const int lane = tid & 31;
    const int mblk = blockIdx.x >> 1;
    const int nblk = blockIdx.x & 1;
    const int row0 = mblk * MTILE;
    const int nbase = nblk * NTILE;

    float* s_b   = reinterpret_cast<float*>(smem + OFF_B);
    float* s_sim = reinterpret_cast<float*>(smem + OFF_SIM);

    // Group 0: x tile + W(0); Group 1: W(1)
#pragma unroll
    for (int k = 0; k < 8; k++) {
        int ci = tid + k * THREADS;          // 2048 chunks per x tile (128 rows x 16)
        int r = ci >> 4, c = ci & 15;
        CP_ASYNC16(sb + OFF_X + swz(r, c), g_xhi + (size_t)(row0 + r) * D_DIM + c * 8);
    }
    issue_w_tile(sb, OFF_W, 0, nbase, tid);
    CP_COMMIT();
    issue_w_tile(sb, OFF_W + 16384u, 1, nbase, tid);
    CP_COMMIT();

    // b (this CTA's 64-col slice) and sim (precomputed) to smem while cp.async flies
#pragma unroll
    for (int i = tid; i < T_DIM * NTILE; i += THREADS)
        s_b[i] = b[(i >> 6) * D_DIM + nbase + (i & 63)];
    {
        int r = tid >> 1, h = tid & 1;       // 128 rows x 2 halves
        float4 s4 = *reinterpret_cast<const float4*>(g_sim + (size_t)(row0 + r) * T_DIM + h * 4);
        s_sim[r * 9 + h * 4 + 0] = s4.x;
        s_sim[r * 9 + h * 4 + 1] = s4.y;
        s_sim[r * 9 + h * 4 + 2] = s4.z;
        s_sim[r * 9 + h * 4 + 3] = s4.w;
    }

    CP_WAIT1();        // group 0 (x + W0) complete
    __syncthreads();   // tiles + sim + b visible

    // ---- Warp tiling: 4(M) x 2(N) grid, warp tile 32x32 ----
    const int wm = wid & 3, wn = wid >> 2;
    const int mbw = wm * 32, nbw = wn * 32;

    // ldmatrix per-lane address parts (swizzled)
    const uint32_t arowb = (uint32_t)((mbw + (lane & 15)) * 256);
    const int     achnk  = lane >> 4;            // 0/1
    const uint32_t browb = (uint32_t)((nbw + (lane & 7) + ((lane >> 4) << 3)) * 256);
    const int     bchnk  = (lane >> 3) & 1;
    const int     bank   = lane & 7;             // == row&7 for both A and B lane->row maps
    const int rql = lane >> 2;
    const int cpl = (lane & 3) * 2;

    float acc[2][4][4];
#pragma unroll
    for (int i = 0; i < 2; i++)
#pragma unroll
        for (int j = 0; j < 4; j++)
#pragma unroll
            for (int e = 0; e < 4; e++) acc[i][j][e] = 0.f;

    for (int t = 0; t < T_DIM; t++) {
        const uint32_t wb = OFF_W + (uint32_t)(t & 1) * 16384u;

        float y[2][4][4];
#pragma unroll
        for (int i = 0; i < 2; i++)
#pragma unroll
            for (int j = 0; j < 4; j++)
#pragma unroll
                for (int e = 0; e < 4; e++) y[i][j][e] = 0.f;

#pragma unroll
        for (int k = 0; k < 8; k++) {
            const uint32_t aoff = arowb + (uint32_t)((((2 * k + achnk) ^ bank)) << 4);
            const uint32_t boff = browb + (uint32_t)((((2 * k + bchnk) ^ bank)) << 4);

            uint32_t ah0, ah1, ah2, ah3, ah4, ah5, ah6, ah7;
            LDM4(ah0, ah1, ah2, ah3, sb + OFF_X + aoff);
            LDM4(ah4, ah5, ah6, ah7, sb + OFF_X + aoff + 16u * 256u);
            uint32_t bh0, bh1, bh2, bh3, bh4, bh5, bh6, bh7;
            LDM4(bh0, bh1, bh2, bh3, sb + wb + boff);
            LDM4(bh4, bh5, bh6, bh7, sb + wb + boff + 16u * 256u);

            MMA16816(y[0][0], ah0, ah1, ah2, ah3, bh0, bh1);
            MMA16816(y[0][1], ah0, ah1, ah2, ah3, bh2, bh3);
            MMA16816(y[0][2], ah0, ah1, ah2, ah3, bh4, bh5);
            MMA16816(y[0][3], ah0, ah1, ah2, ah3, bh6, bh7);
            MMA16816(y[1][0], ah4, ah5, ah6, ah7, bh0, bh1);
            MMA16816(y[1][1], ah4, ah5, ah6, ah7, bh2, bh3);
            MMA16816(y[1][2], ah4, ah5, ah6, ah7, bh4, bh5);
            MMA16816(y[1][3], ah4, ah5, ah6, ah7, bh6, bh7);
        }

        // fold: acc += sim_row * (y + bias_col)
#pragma unroll
        for (int mt = 0; mt < 2; mt++) {
            const int rloc = mbw + mt * 16 + rql;
            const float s0 = s_sim[rloc * 9 + t];
            const float s1 = s_sim[(rloc + 8) * 9 + t];
#pragma unroll
            for (int nt = 0; nt < 4; nt++) {
                const int c = nbw + nt * 8 + cpl;          // local col 0..63
                const float bb0 = s_b[t * NTILE + c];
                const float bb1 = s_b[t * NTILE + c + 1];
                acc[mt][nt][0] = fmaf(s0, y[mt][nt][0] + bb0, acc[mt][nt][0]);
                acc[mt][nt][1] = fmaf(s0, y[mt][nt][1] + bb1, acc[mt][nt][1]);
                acc[mt][nt][2] = fmaf(s1, y[mt][nt][2] + bb0, acc[mt][nt][2]);
                acc[mt][nt][3] = fmaf(s1, y[mt][nt][3] + bb1, acc[mt][nt][3]);
            }
        }

        // pipeline: refill the buffer we just finished with W(t+2)
        if (t < T_DIM - 2) {
            __syncthreads();
            issue_w_tile(sb, OFF_W + (uint32_t)(t & 1) * 16384u, t + 2, nbase, tid);
            CP_COMMIT();
        }
        if (t < T_DIM - 1) {
            if (t < T_DIM - 2) { CP_WAIT1(); } else { CP_WAIT0(); }
            __syncthreads();
        }
    }

    // ---- Epilogue: residual (exact fp32 x from gmem) + store ----
#pragma unroll
    for (int mt = 0; mt < 2; mt++) {
        const int rg0 = row0 + mbw + mt * 16 + rql;
        const int rg1 = rg0 + 8;
#pragma unroll
        for (int nt = 0; nt < 4; nt++) {
            const int c = nbase + nbw + nt * 8 + cpl;       // global col
            float2 xv0 = *reinterpret_cast<const float2*>(x + (size_t)rg0 * D_DIM + c);
            float2 o0  = make_float2(acc[mt][nt][0] + xv0.x, acc[mt][nt][1] + xv0.y);
            *reinterpret_cast<float2*>(out + (size_t)rg0 * D_DIM + c) = o0;
            float2 xv1 = *reinterpret_cast<const float2*>(x + (size_t)rg1 * D_DIM + c);
            float2 o1  = make_float2(acc[mt][nt][2] + xv1.x, acc[mt][nt][3] + xv1.y);
            *reinterpret_cast<float2*>(out + (size_t)rg1 * D_DIM + c) = o1;
        }
    }
}

extern "C" void kernel_launch(void* const* d_in, const int* in_sizes, int n_in,
                              void* d_out, int out_size)
{
    (void)n_in; (void)out_size;
    const float* x = (const float*)d_in[0];   // [B,S,D]
    const float* W = (const float*)d_in[1];   // [T,D,D]
    const float* b = (const float*)d_in[2];   // [T,D]
    const float* p = (const float*)d_in[3];   // [T,1,D]
    float* out = (float*)d_out;

    const int nrows = in_sizes[0] / D_DIM;    // 65536
    const int grid  = (nrows / MTILE) * 2;    // 1024 (M-blocks x 2 N-halves)

    conv_kernel<<<2048, 256>>>(x, W);
    gate_kernel<<<nrows / 8, 256>>>(x, p);

    cudaFuncSetAttribute(dt_mma_kernel,
                         cudaFuncAttributeMaxDynamicSharedMemorySize, SMEM_TOTAL);
    dt_mma_kernel<<<grid, THREADS, SMEM_TOTAL>>>(x, b, out);
}

// round 12
// speedup vs baseline: 1.3550x; 1.1598x over previous
#include <cuda_runtime.h>
#include <cuda_fp16.h>
#include <cstdint>
#include <math.h>

// DataTransformer via mma.sync, pure fp16 single-pass GEMM (fp32 accumulate):
//   out[r,e] = sum_t softmax_t(cos(x_r,p_t)) * (x_r . W_t[e,:] + b_t[e]) + x[r,e]
// x [65536,128] f32, W [8,128,128] (W[t][e][d]), b [8,128], p [8,128].
// x converted fp32->fp16 in-kernel; conv kernel handles W only.
// CTA tile: 128 rows x 64 cols, 256 threads, warp grid 4x2 (tile 32x32). 2 CTAs/SM.

#define D_DIM   128
#define T_DIM   8
#define MTILE   128
#define NTILE   64
#define THREADS 256
#define NROWS   65536

// fp16 W scratch (static __device__ array: allowed scratch form)
__device__ __half g_whi[T_DIM * D_DIM * D_DIM];

// ---- smem layout (bytes). Tiles use 256 B rows + XOR-of-16B-chunk swizzle ----
#define OFF_X    0u         // 128x128 fp16 = 32768
#define OFF_W    32768u     // 2 buffers x (64x128 fp16 = 16384) = 32768
#define OFF_P    65536u     // 8*128 f32 = 4096
#define OFF_B    69632u     // 8*64 f32 = 2048
#define OFF_SIM  71680u     // 128*9*4 = 4608 (fp32, stride 9)
#define OFF_PN2  76288u     // 8 f32
#define SMEM_TOTAL 76320

__device__ __forceinline__ uint32_t smem_u32(const void* p) {
    uint32_t a;
    asm("{ .reg .u64 t; cvta.to.shared.u64 t, %1; cvt.u32.u64 %0, t; }" : "=r"(a) : "l"(p));
    return a;
}

#define CP_ASYNC16(dst, src) \
    asm volatile("cp.async.cg.shared.global [%0], [%1], 16;" :: "r"(dst), "l"(src) : "memory")
#define CP_COMMIT() asm volatile("cp.async.commit_group;" ::: "memory")
#define CP_WAIT1()  asm volatile("cp.async.wait_group 1;" ::: "memory")
#define CP_WAIT0()  asm volatile("cp.async.wait_group 0;" ::: "memory")

#define LDM4(r0, r1, r2, r3, addr) \
    asm volatile("ldmatrix.sync.aligned.m8n8.x4.shared.b16 {%0,%1,%2,%3}, [%4];" \
        : "=r"(r0), "=r"(r1), "=r"(r2), "=r"(r3) : "r"(addr))

#define MMA16816(d, a0, a1, a2, a3, b0, b1) \
    asm volatile("mma.sync.aligned.m16n8k16.row.col.f32.f16.f16.f32 " \
        "{%0,%1,%2,%3}, {%4,%5,%6,%7}, {%8,%9}, {%0,%1,%2,%3};" \
        : "+f"((d)[0]), "+f"((d)[1]), "+f"((d)[2]), "+f"((d)[3]) \
        : "r"(a0), "r"(a1), "r"(a2), "r"(a3), "r"(b0), "r"(b1))

// swizzled byte offset of 16B chunk (r, c), c in [0,16), 256 B rows
__device__ __forceinline__ uint32_t swz(int r, int c) {
    return (uint32_t)(r * 256 + ((c ^ (r & 7)) << 4));
}

// ===================== Kernel 1: W fp32 -> fp16 preconvert (tiny) =====================
__global__ void conv_kernel(const float* __restrict__ W)
{
    const int W4 = T_DIM * D_DIM * D_DIM / 4;   // 32768 float4
    int i = blockIdx.x * blockDim.x + threadIdx.x;
    if (i < W4) {
        float4 v = reinterpret_cast<const float4*>(W)[i];
        float vf[4] = {v.x, v.y, v.z, v.w};
        uint32_t hw[4];
#pragma unroll
        for (int e = 0; e < 4; e++)
            hw[e] = (uint32_t)__half_as_ushort(__float2half_rn(vf[e]));
        reinterpret_cast<uint2*>(g_whi)[i] =
            make_uint2(hw[0] | (hw[1] << 16), hw[2] | (hw[3] << 16));
    }
}

// ===================== Kernel 2: GEMM + gating + fold =====================
__device__ __forceinline__ void issue_w_tile(uint32_t sb, uint32_t wbuf, int t, int nbase, int tid)
{
    const size_t wb = (size_t)t * (D_DIM * D_DIM) + (size_t)nbase * D_DIM;
#pragma unroll
    for (int k = 0; k < 4; k++) {
        int ci = tid + k * THREADS;          // 16B chunk index, 1024 per tile (64 rows x 16)
        int r = ci >> 4, c = ci & 15;
        CP_ASYNC16(sb + wbuf + swz(r, c), g_whi + wb + r * D_DIM + c * 8);
    }
}

__global__ void __launch_bounds__(THREADS, 2)
dt_mma_kernel(const float* __restrict__ x,
              const float* __restrict__ b,
              const float* __restrict__ p,
              float* __restrict__ out)
{
    extern __shared__ char smem[];
    const uint32_t sb = smem_u32(smem);
    const int tid  = threadIdx.x;
    const int wid  = tid >> 5;
    const int lane = tid & 31;
    const int mblk = blockIdx.x >> 1;
    const int nblk = blockIdx.x & 1;
    const int row0 = mblk * MTILE;
    const int nbase = nblk * NTILE;

    float* s_p   = reinterpret_cast<float*>(smem + OFF_P);
    float* s_b   = reinterpret_cast<float*>(smem + OFF_B);
    float* s_sim = reinterpret_cast<float*>(smem + OFF_SIM);
    float* s_pn2 = reinterpret_cast<float*>(smem + OFF_PN2);

    // W(0), W(1) via cp.async first (they fly during convert + gating)
    issue_w_tile(sb, OFF_W, 0, nbase, tid);
    CP_COMMIT();
    issue_w_tile(sb, OFF_W + 16384u, 1, nbase, tid);
    CP_COMMIT();

    // p (full) and b (this CTA's 64-col slice) to smem
#pragma unroll
    for (int i = tid; i < T_DIM * D_DIM; i += THREADS) s_p[i] = p[i];
#pragma unroll
    for (int i = tid; i < T_DIM * NTILE; i += THREADS)
        s_b[i] = b[(i >> 6) * D_DIM + nbase + (i & 63)];

    // x tile: fp32 gmem -> fp16 swizzled smem (2048 16B chunks, 8 per thread)
#pragma unroll
    for (int k = 0; k < 8; k++) {
        int ci = tid + k * THREADS;
        int r = ci >> 4, c = ci & 15;
        const float4* src = reinterpret_cast<const float4*>(
            x + (size_t)(row0 + r) * D_DIM + c * 8);
        float4 v0 = src[0], v1 = src[1];
        uint32_t hw[4];
        hw[0] = (uint32_t)__half_as_ushort(__float2half_rn(v0.x))
              | ((uint32_t)__half_as_ushort(__float2half_rn(v0.y)) << 16);
        hw[1] = (uint32_t)__half_as_ushort(__float2half_rn(v0.z))
              | ((uint32_t)__half_as_ushort(__float2half_rn(v0.w)) << 16);
        hw[2] = (uint32_t)__half_as_ushort(__float2half_rn(v1.x))
              | ((uint32_t)__half_as_ushort(__float2half_rn(v1.y)) << 16);
        hw[3] = (uint32_t)__half_as_ushort(__float2half_rn(v1.z))
              | ((uint32_t)__half_as_ushort(__float2half_rn(v1.w)) << 16);
        *reinterpret_cast<uint4*>(smem + OFF_X + swz(r, c)) =
            make_uint4(hw[0], hw[1], hw[2], hw[3]);
    }

    __syncthreads();   // s_p visible for gating

    // ---- Gating (exact fp32, float4 s_p loads; overlaps W cp.async) ----
    if (tid < T_DIM) {
        float pn2 = 0.f;
        const float4* pr = reinterpret_cast<const float4*>(s_p + tid * D_DIM);
#pragma unroll 8
        for (int i = 0; i < 32; i++) {
            float4 pv = pr[i];
            pn2 += pv.x * pv.x + pv.y * pv.y + pv.z * pv.z + pv.w * pv.w;
        }
        s_pn2[tid] = pn2;
    }
    float dots[T_DIM], xn2 = 0.f;
    if (tid < MTILE) {
#pragma unroll
        for (int t = 0; t < T_DIM; t++) dots[t] = 0.f;
        const float4* xr = reinterpret_cast<const float4*>(x + (size_t)(row0 + tid) * D_DIM);
#pragma unroll 4
        for (int i = 0; i < 32; i++) {
            float4 v = xr[i];
            xn2 += v.x * v.x + v.y * v.y + v.z * v.z + v.w * v.w;
#pragma unroll
            for (int t = 0; t < T_DIM; t++) {
                float4 pv = *reinterpret_cast<const float4*>(s_p + t * D_DIM + i * 4);
                dots[t] += v.x * pv.x + v.y * pv.y + v.z * pv.z + v.w * pv.w;
            }
        }
    }
    __syncthreads();   // s_pn2 ready
    if (tid < MTILE) {
        float xn = sqrtf(xn2);
        float cosv[T_DIM], m = -1e30f;
#pragma unroll
        for (int t = 0; t < T_DIM; t++) {
            cosv[t] = dots[t] / (xn * sqrtf(s_pn2[t]));
            m = fmaxf(m, cosv[t]);
        }
        float ev[T_DIM], sum = 0.f;
#pragma unroll
        for (int t = 0; t < T_DIM; t++) { ev[t] = expf(cosv[t] - m); sum += ev[t]; }
        float inv = 1.f / sum;
#pragma unroll
        for (int t = 0; t < T_DIM; t++) s_sim[tid * 9 + t] = ev[t] * inv;
    }

    CP_WAIT1();        // W(0) complete (W(1) may still be in flight)
    __syncthreads();   // x tile (STS) + W0 + sim visible to all

    // ---- Warp tiling: 4(M) x 2(N) grid, warp tile 32x32 ----
    const int wm = wid & 3, wn = wid >> 2;
    const int mbw = wm * 32, nbw = wn * 32;

    // ldmatrix per-lane address parts (swizzled)
    const uint32_t arowb = (uint32_t)((mbw + (lane & 15)) * 256);
    const int     achnk  = lane >> 4;            // 0/1
    const uint32_t browb = (uint32_t)((nbw + (lane & 7) + ((lane >> 4) << 3)) * 256);
    const int     bchnk  = (lane >> 3) & 1;
    const int     bank   = lane & 7;             // == row&7 for both A and B lane->row maps
    const int rql = lane >> 2;
    const int cpl = (lane & 3) * 2;

    float acc[2][4][4];
#pragma unroll
    for (int i = 0; i < 2; i++)
#pragma unroll
        for (int j = 0; j < 4; j++)
#pragma unroll
            for (int e = 0; e < 4; e++) acc[i][j][e] = 0.f;

    for (int t = 0; t < T_DIM; t++) {
        const uint32_t wb = OFF_W + (uint32_t)(t & 1) * 16384u;

        float y[2][4][4];
#pragma unroll
        for (int i = 0; i < 2; i++)
#pragma unroll
            for (int j = 0; j < 4; j++)
#pragma unroll
                for (int e = 0; e < 4; e++) y[i][j][e] = 0.f;

#pragma unroll
        for (int k = 0; k < 8; k++) {
            const uint32_t aoff = arowb + (uint32_t)((((2 * k + achnk) ^ bank)) << 4);
            const uint32_t boff = browb + (uint32_t)((((2 * k + bchnk) ^ bank)) << 4);

            uint32_t ah0, ah1, ah2, ah3, ah4, ah5, ah6, ah7;
            LDM4(ah0, ah1, ah2, ah3, sb + OFF_X + aoff);
            LDM4(ah4, ah5, ah6, ah7, sb + OFF_X + aoff + 16u * 256u);
            uint32_t bh0, bh1, bh2, bh3, bh4, bh5, bh6, bh7;
            LDM4(bh0, bh1, bh2, bh3, sb + wb + boff);
            LDM4(bh4, bh5, bh6, bh7, sb + wb + boff + 16u * 256u);

            MMA16816(y[0][0], ah0, ah1, ah2, ah3, bh0, bh1);
            MMA16816(y[0][1], ah0, ah1, ah2, ah3, bh2, bh3);
            MMA16816(y[0][2], ah0, ah1, ah2, ah3, bh4, bh5);
            MMA16816(y[0][3], ah0, ah1, ah2, ah3, bh6, bh7);
            MMA16816(y[1][0], ah4, ah5, ah6, ah7, bh0, bh1);
            MMA16816(y[1][1], ah4, ah5, ah6, ah7, bh2, bh3);
            MMA16816(y[1][2], ah4, ah5, ah6, ah7, bh4, bh5);
            MMA16816(y[1][3], ah4, ah5, ah6, ah7, bh6, bh7);
        }

        // fold: acc += sim_row * (y + bias_col)
#pragma unroll
        for (int mt = 0; mt < 2; mt++) {
            const int rloc = mbw + mt * 16 + rql;
            const float s0 = s_sim[rloc * 9 + t];
            const float s1 = s_sim[(rloc + 8) * 9 + t];
#pragma unroll
            for (int nt = 0; nt < 4; nt++) {
                const int c = nbw + nt * 8 + cpl;          // local col 0..63
                const float bb0 = s_b[t * NTILE + c];
                const float bb1 = s_b[t * NTILE + c + 1];
                acc[mt][nt][0] = fmaf(s0, y[mt][nt][0] + bb0, acc[mt][nt][0]);
                acc[mt][nt][1] = fmaf(s0, y[mt][nt][1] + bb1, acc[mt][nt][1]);
                acc[mt][nt][2] = fmaf(s1, y[mt][nt][2] + bb0, acc[mt][nt][2]);
                acc[mt][nt][3] = fmaf(s1, y[mt][nt][3] + bb1, acc[mt][nt][3]);
            }
        }

        // pipeline: refill the buffer we just finished with W(t+2)
        if (t < T_DIM - 2) {
            __syncthreads();
            issue_w_tile(sb, OFF_W + (uint32_t)(t & 1) * 16384u, t + 2, nbase, tid);
            CP_COMMIT();
        }
        if (t < T_DIM - 1) {
            if (t < T_DIM - 2) { CP_WAIT1(); } else { CP_WAIT0(); }
            __syncthreads();
        }
    }

    // ---- Epilogue: residual (exact fp32 x from gmem) + store ----
#pragma unroll
    for (int mt = 0; mt < 2; mt++) {
        const int rg0 = row0 + mbw + mt * 16 + rql;
        const int rg1 = rg0 + 8;
#pragma unroll
        for (int nt = 0; nt < 4; nt++) {
            const int c = nbase + nbw + nt * 8 + cpl;       // global col
            float2 xv0 = *reinterpret_cast<const float2*>(x + (size_t)rg0 * D_DIM + c);
            float2 o0  = make_float2(acc[mt][nt][0] + xv0.x, acc[mt][nt][1] + xv0.y);
            *reinterpret_cast<float2*>(out + (size_t)rg0 * D_DIM + c) = o0;
            float2 xv1 = *reinterpret_cast<const float2*>(x + (size_t)rg1 * D_DIM + c);
            float2 o1  = make_float2(acc[mt][nt][2] + xv1.x, acc[mt][nt][3] + xv1.y);
            *reinterpret_cast<float2*>(out + (size_t)rg1 * D_DIM + c) = o1;
        }
    }
}

extern "C" void kernel_launch(void* const* d_in, const int* in_sizes, int n_in,
                              void* d_out, int out_size)
{
    (void)n_in; (void)out_size;
    const float* x = (const float*)d_in[0];   // [B,S,D]
    const float* W = (const float*)d_in[1];   // [T,D,D]
    const float* b = (const float*)d_in[2];   // [T,D]
    const float* p = (const float*)d_in[3];   // [T,1,D]
    float* out = (float*)d_out;

    const int nrows = in_sizes[0] / D_DIM;    // 65536
    const int grid  = (nrows / MTILE) * 2;    // 1024 (M-blocks x 2 N-halves)

    conv_kernel<<<128, 256>>>(W);             // W only: 32768 float4

    cudaFuncSetAttribute(dt_mma_kernel,
                         cudaFuncAttributeMaxDynamicSharedMemorySize, SMEM_TOTAL);
    dt_mma_kernel<<<grid, THREADS, SMEM_TOTAL>>>(x, b, p, out);
}